// round 2
// baseline (speedup 1.0000x reference)
#include <cuda_runtime.h>

// ---------------- constants ----------------
#define G       100
#define G3      (G * G * G)
#define NPART   13500
#define NSUB    600
#define SPF     30          // substeps per frame
#define BOUNDC  3

__device__ __forceinline__ constexpr float cDT()     { return 5e-4f; }
__device__ __forceinline__ constexpr float cINVDX()  { return 100.0f; }
__device__ __forceinline__ constexpr float cDX()     { return 0.01f; }
__device__ __forceinline__ constexpr float cMU()     { return 1.0e5f / (2.0f * 1.3f); }            // 38461.54
__device__ __forceinline__ constexpr float cLAM()    { return 1.0e5f * 0.3f / (1.3f * 0.4f); }     // 57692.31
__device__ __forceinline__ constexpr float cPVOL()   { return 0.005f * 0.005f * 0.005f; }
__device__ __forceinline__ constexpr float cPMASS()  { return 0.005f * 0.005f * 0.005f * 3000.0f; }
__device__ __forceinline__ constexpr float cSPRE()   { return -cDT() * cPVOL() * 4.0f * cINVDX() * cINVDX(); }
__device__ __forceinline__ constexpr float cDINV()   { return 4.0f * cINVDX() * cINVDX(); }        // 40000
__device__ __forceinline__ constexpr float cGRAVY()  { return -9.8f; }

// ---------------- persistent device state ----------------
// 3 rotating grid buffers: (vx, vy, vz, m) per cell. 48 MB total (BSS, zero-init).
__device__ float4 g_grid[3][G3];
__device__ float  g_x[NPART * 3];      // particle positions
__device__ float  g_vel0[NPART * 3];   // initial velocities (only read at t==1)
__device__ float  g_F[NPART * 9];      // deformation gradients
__device__ int4   g_baseh[2][NPART];   // base-cell history (for re-zeroing buffers)

// ---------------- helpers ----------------
__device__ __forceinline__ float wsel(int o, float a, float b, float c) {
    return (o == 0) ? a : ((o == 1) ? b : c);
}

#define WREDUCE(v)                                            \
    do {                                                      \
        v += __shfl_xor_sync(0xffffffffu, v, 16);             \
        v += __shfl_xor_sync(0xffffffffu, v, 8);              \
        v += __shfl_xor_sync(0xffffffffu, v, 4);              \
        v += __shfl_xor_sync(0xffffffffu, v, 2);              \
        v += __shfl_xor_sync(0xffffffffu, v, 1);              \
    } while (0)

// ---------------- init kernels ----------------
__global__ void k_zero_grid() {
    int i = blockIdx.x * blockDim.x + threadIdx.x;
    if (i < 3 * G3) reinterpret_cast<float4*>(g_grid)[i] = make_float4(0.f, 0.f, 0.f, 0.f);
}

__global__ void k_init_part(const float* __restrict__ q, const float* __restrict__ qd) {
    int p = blockIdx.x * blockDim.x + threadIdx.x;
    if (p >= NPART) return;
    g_x[p * 3 + 0] = q[p * 3 + 0];
    g_x[p * 3 + 1] = q[p * 3 + 1];
    g_x[p * 3 + 2] = q[p * 3 + 2];
    g_vel0[p * 3 + 0] = qd[p * 3 + 0];
    g_vel0[p * 3 + 1] = qd[p * 3 + 1];
    g_vel0[p * 3 + 2] = qd[p * 3 + 2];
#pragma unroll
    for (int i = 0; i < 9; i++) g_F[p * 9 + i] = (i % 4 == 0) ? 1.0f : 0.0f;  // identity
}

// ---------------- fused substep kernel (warp per particle) ----------------
// Kernel t (1..600):
//   - zero buf[(t+1)%3] at cells touched at substep t-2   (t >= 3)
//   - G2P of substep t-1 from buf[(t-1)%3] with on-the-fly normalize+BC (t >= 2)
//   - particle update (x += DT*v), F update, neo-Hookean stress
//   - P2G of substep t into buf[t%3] via atomics; record base cells
__global__ void __launch_bounds__(128) k_mpm_step(int t, const float* __restrict__ vptr) {
    unsigned gtid = blockIdx.x * blockDim.x + threadIdx.x;
    int p = gtid >> 5;
    if (p >= NPART) return;
    int lane = threadIdx.x & 31;
    int oi = lane / 9;
    int oj = (lane / 3) % 3;
    int ok = lane % 3;
    bool act = (lane < 27);

    const int bufG = (t + 2) % 3;  // (t-1) mod 3
    const int bufS = t % 3;
    const int bufZ = (t + 1) % 3;  // buffer scattered at t-2

    const float vscalar = __ldg(vptr);

    // --- zero the buffer used two substeps ago (touched-cell set only) ---
    if (t >= 3) {
        int4 ob = g_baseh[t & 1][p];  // base of substep t-2 (slot about to be overwritten)
        if (act) {
            int nx = min(max(ob.x + oi, 0), G - 1);
            int ny = min(max(ob.y + oj, 0), G - 1);
            int nz = min(max(ob.z + ok, 0), G - 1);
            g_grid[bufZ][(nx * G + ny) * G + nz] = make_float4(0.f, 0.f, 0.f, 0.f);
        }
    }

    float px = g_x[p * 3 + 0];
    float py = g_x[p * 3 + 1];
    float pz = g_x[p * 3 + 2];

    float vx, vy, vz;
    float c00, c01, c02, c10, c11, c12, c20, c21, c22;

    if (t >= 2) {
        // --- G2P for substep t-1: recompute weights from current x ---
        float gx = px * cINVDX(), gy = py * cINVDX(), gz = pz * cINVDX();
        float bxf = floorf(gx - 0.5f), byf = floorf(gy - 0.5f), bzf = floorf(gz - 0.5f);
        int bx = (int)bxf, by = (int)byf, bz = (int)bzf;
        float fx = gx - bxf, fy = gy - byf, fz = gz - bzf;

        float wx0 = 0.5f * (1.5f - fx) * (1.5f - fx);
        float wx1 = 0.75f - (fx - 1.0f) * (fx - 1.0f);
        float wx2 = 0.5f * (fx - 0.5f) * (fx - 0.5f);
        float wy0 = 0.5f * (1.5f - fy) * (1.5f - fy);
        float wy1 = 0.75f - (fy - 1.0f) * (fy - 1.0f);
        float wy2 = 0.5f * (fy - 0.5f) * (fy - 0.5f);
        float wz0 = 0.5f * (1.5f - fz) * (1.5f - fz);
        float wz1 = 0.75f - (fz - 1.0f) * (fz - 1.0f);
        float wz2 = 0.5f * (fz - 0.5f) * (fz - 0.5f);

        float w = act ? (wsel(oi, wx0, wx1, wx2) * wsel(oj, wy0, wy1, wy2) * wsel(ok, wz0, wz1, wz2))
                      : 0.0f;

        int nx = min(max(bx + oi, 0), G - 1);
        int ny = min(max(by + oj, 0), G - 1);
        int nz = min(max(bz + ok, 0), G - 1);
        float4 cell = g_grid[bufG][(nx * G + ny) * G + nz];

        float inv = 1.0f / (cell.w + vscalar);
        float gvx = cell.x * inv, gvy = cell.y * inv, gvz = cell.z * inv;
        if ((nx < BOUNDC && gvx < 0.f) || (nx >= G - BOUNDC && gvx > 0.f)) gvx = 0.f;
        if ((ny < BOUNDC && gvy < 0.f) || (ny >= G - BOUNDC && gvy > 0.f)) gvy = 0.f;
        if ((nz < BOUNDC && gvz < 0.f) || (nz >= G - BOUNDC && gvz > 0.f)) gvz = 0.f;

        float dpx = ((float)oi - fx) * cDX();
        float dpy = ((float)oj - fy) * cDX();
        float dpz = ((float)ok - fz) * cDX();

        float wgx = w * gvx, wgy = w * gvy, wgz = w * gvz;
        vx = wgx; vy = wgy; vz = wgz;
        c00 = wgx * dpx; c01 = wgx * dpy; c02 = wgx * dpz;
        c10 = wgy * dpx; c11 = wgy * dpy; c12 = wgy * dpz;
        c20 = wgz * dpx; c21 = wgz * dpy; c22 = wgz * dpz;

        WREDUCE(vx);  WREDUCE(vy);  WREDUCE(vz);
        WREDUCE(c00); WREDUCE(c01); WREDUCE(c02);
        WREDUCE(c10); WREDUCE(c11); WREDUCE(c12);
        WREDUCE(c20); WREDUCE(c21); WREDUCE(c22);

        c00 *= cDINV(); c01 *= cDINV(); c02 *= cDINV();
        c10 *= cDINV(); c11 *= cDINV(); c12 *= cDINV();
        c20 *= cDINV(); c21 *= cDINV(); c22 *= cDINV();

        // position update (carry into substep t)
        px += cDT() * vx; py += cDT() * vy; pz += cDT() * vz;
    } else {
        vx = g_vel0[p * 3 + 0]; vy = g_vel0[p * 3 + 1]; vz = g_vel0[p * 3 + 2];
        c00 = c01 = c02 = c10 = c11 = c12 = c20 = c21 = c22 = 0.0f;
    }

    // --- F update: F = (I + DT*C) * F ---
    float f00 = g_F[p * 9 + 0], f01 = g_F[p * 9 + 1], f02 = g_F[p * 9 + 2];
    float f10 = g_F[p * 9 + 3], f11 = g_F[p * 9 + 4], f12 = g_F[p * 9 + 5];
    float f20 = g_F[p * 9 + 6], f21 = g_F[p * 9 + 7], f22 = g_F[p * 9 + 8];

    float a00 = 1.0f + cDT() * c00, a01 = cDT() * c01, a02 = cDT() * c02;
    float a10 = cDT() * c10, a11 = 1.0f + cDT() * c11, a12 = cDT() * c12;
    float a20 = cDT() * c20, a21 = cDT() * c21, a22 = 1.0f + cDT() * c22;

    float F00 = a00 * f00 + a01 * f10 + a02 * f20;
    float F01 = a00 * f01 + a01 * f11 + a02 * f21;
    float F02 = a00 * f02 + a01 * f12 + a02 * f22;
    float F10 = a10 * f00 + a11 * f10 + a12 * f20;
    float F11 = a10 * f01 + a11 * f11 + a12 * f21;
    float F12 = a10 * f02 + a11 * f12 + a12 * f22;
    float F20 = a20 * f00 + a21 * f10 + a22 * f20;
    float F21 = a20 * f01 + a21 * f11 + a22 * f21;
    float F22 = a20 * f02 + a21 * f12 + a22 * f22;

    // --- neo-Hookean PK1 via cofactors: FinvT = cof(F)/J ---
    float co00 = F11 * F22 - F12 * F21;
    float co01 = F12 * F20 - F10 * F22;
    float co02 = F10 * F21 - F11 * F20;
    float co10 = F02 * F21 - F01 * F22;
    float co11 = F00 * F22 - F02 * F20;
    float co12 = F01 * F20 - F00 * F21;
    float co20 = F01 * F12 - F02 * F11;
    float co21 = F02 * F10 - F00 * F12;
    float co22 = F00 * F11 - F01 * F10;
    float J = F00 * co00 + F01 * co01 + F02 * co02;

    float logJ = logf(fmaxf(J, 1e-6f));
    float coef = (cLAM() * logJ - cMU()) / J;   // P = MU*F + coef*cof

    float P00 = cMU() * F00 + coef * co00;
    float P01 = cMU() * F01 + coef * co01;
    float P02 = cMU() * F02 + coef * co02;
    float P10 = cMU() * F10 + coef * co10;
    float P11 = cMU() * F11 + coef * co11;
    float P12 = cMU() * F12 + coef * co12;
    float P20 = cMU() * F20 + coef * co20;
    float P21 = cMU() * F21 + coef * co21;
    float P22 = cMU() * F22 + coef * co22;

    // stress = SPRE * P * F^T ; affine = stress + P_MASS * C
    float A00 = cSPRE() * (P00 * F00 + P01 * F01 + P02 * F02) + cPMASS() * c00;
    float A01 = cSPRE() * (P00 * F10 + P01 * F11 + P02 * F12) + cPMASS() * c01;
    float A02 = cSPRE() * (P00 * F20 + P01 * F21 + P02 * F22) + cPMASS() * c02;
    float A10 = cSPRE() * (P10 * F00 + P11 * F01 + P12 * F02) + cPMASS() * c10;
    float A11 = cSPRE() * (P10 * F10 + P11 * F11 + P12 * F12) + cPMASS() * c11;
    float A12 = cSPRE() * (P10 * F20 + P11 * F21 + P12 * F22) + cPMASS() * c12;
    float A20 = cSPRE() * (P20 * F00 + P21 * F01 + P22 * F02) + cPMASS() * c20;
    float A21 = cSPRE() * (P20 * F10 + P21 * F11 + P22 * F12) + cPMASS() * c21;
    float A22 = cSPRE() * (P20 * F20 + P21 * F21 + P22 * F22) + cPMASS() * c22;

    // --- P2G for substep t ---
    float gx2 = px * cINVDX(), gy2 = py * cINVDX(), gz2 = pz * cINVDX();
    float bxf2 = floorf(gx2 - 0.5f), byf2 = floorf(gy2 - 0.5f), bzf2 = floorf(gz2 - 0.5f);
    int bx2 = (int)bxf2, by2 = (int)byf2, bz2 = (int)bzf2;
    float fx2 = gx2 - bxf2, fy2 = gy2 - byf2, fz2 = gz2 - bzf2;

    float sx0 = 0.5f * (1.5f - fx2) * (1.5f - fx2);
    float sx1 = 0.75f - (fx2 - 1.0f) * (fx2 - 1.0f);
    float sx2 = 0.5f * (fx2 - 0.5f) * (fx2 - 0.5f);
    float sy0 = 0.5f * (1.5f - fy2) * (1.5f - fy2);
    float sy1 = 0.75f - (fy2 - 1.0f) * (fy2 - 1.0f);
    float sy2 = 0.5f * (fy2 - 0.5f) * (fy2 - 0.5f);
    float sz0 = 0.5f * (1.5f - fz2) * (1.5f - fz2);
    float sz1 = 0.75f - (fz2 - 1.0f) * (fz2 - 1.0f);
    float sz2 = 0.5f * (fz2 - 0.5f) * (fz2 - 0.5f);

    __syncwarp();  // all lanes are done reading g_baseh before lane 0 overwrites it

    if (lane == 0) {
        g_x[p * 3 + 0] = px; g_x[p * 3 + 1] = py; g_x[p * 3 + 2] = pz;
        g_F[p * 9 + 0] = F00; g_F[p * 9 + 1] = F01; g_F[p * 9 + 2] = F02;
        g_F[p * 9 + 3] = F10; g_F[p * 9 + 4] = F11; g_F[p * 9 + 5] = F12;
        g_F[p * 9 + 6] = F20; g_F[p * 9 + 7] = F21; g_F[p * 9 + 8] = F22;
        g_baseh[t & 1][p] = make_int4(bx2, by2, bz2, 0);
    }

    if (act) {
        float w2 = wsel(oi, sx0, sx1, sx2) * wsel(oj, sy0, sy1, sy2) * wsel(ok, sz0, sz1, sz2);
        float dpx = ((float)oi - fx2) * cDX();
        float dpy = ((float)oj - fy2) * cDX();
        float dpz = ((float)ok - fz2) * cDX();

        float mx = w2 * (cPMASS() * vx + A00 * dpx + A01 * dpy + A02 * dpz);
        float my = w2 * (cPMASS() * (vy + cDT() * cGRAVY()) + A10 * dpx + A11 * dpy + A12 * dpz);
        float mz = w2 * (cPMASS() * vz + A20 * dpx + A21 * dpy + A22 * dpz);

        int nx2 = min(max(bx2 + oi, 0), G - 1);
        int ny2 = min(max(by2 + oj, 0), G - 1);
        int nz2 = min(max(bz2 + ok, 0), G - 1);
        float4* cell = &g_grid[bufS][(nx2 * G + ny2) * G + nz2];
        atomicAdd(&cell->x, mx);
        atomicAdd(&cell->y, my);
        atomicAdd(&cell->z, mz);
        atomicAdd(&cell->w, w2 * cPMASS());
    }
}

// ---------------- frame output ----------------
__global__ void k_out_frame(float* __restrict__ out, const float* __restrict__ vptr, int buf) {
    int i = blockIdx.x * blockDim.x + threadIdx.x;
    if (i < G3) out[i] = g_grid[buf][i].w + vptr[0];
}

// ---------------- launcher ----------------
extern "C" void kernel_launch(void* const* d_in, const int* in_sizes, int n_in,
                              void* d_out, int out_size) {
    const float* v  = (const float*)d_in[0];
    const float* q  = (const float*)d_in[1];
    const float* qd = (const float*)d_in[2];
    float* out = (float*)d_out;
    (void)in_sizes; (void)n_in; (void)out_size;

    k_zero_grid<<<(3 * G3 + 255) / 256, 256>>>();
    k_init_part<<<(NPART + 127) / 128, 128>>>(q, qd);

    const int blocks = (NPART * 32 + 127) / 128;  // warp per particle
    for (int t = 1; t <= NSUB; t++) {
        k_mpm_step<<<blocks, 128>>>(t, v);
        if (t % SPF == 0) {
            int f = t / SPF - 1;
            k_out_frame<<<(G3 + 255) / 256, 256>>>(out + (size_t)f * G3, v, t % 3);
        }
    }
}

// round 3
// speedup vs baseline: 3.0173x; 3.0173x over previous
#include <cuda_runtime.h>

// ---------------- constants ----------------
#define G       100
#define G3      (G * G * G)
#define NPART   13500
#define NSUB    600
#define SPF     30          // substeps per frame
#define BOUNDC  3

#define DT_     5e-4f
#define INVDX_  100.0f
#define DX_     0.01f
#define MU_     (1.0e5f / 2.6f)           // E/(2(1+nu))
#define LAM_    (0.3e5f / 0.52f)          // E*nu/((1+nu)(1-2nu))
#define PVOL_   (0.005f * 0.005f * 0.005f)
#define PMASS_  (PVOL_ * 3000.0f)
#define SPRE_   (-DT_ * PVOL_ * 4.0f * INVDX_ * INVDX_)
#define DINV_   (4.0f * INVDX_ * INVDX_)
#define GRAVY_  (-9.8f)

// ---------------- persistent device state ----------------
__device__ float4 g_grid[3][G3];        // (vx,vy,vz,m) x 3 rotating buffers
__device__ float4 g_x4[NPART];          // positions (w unused)
__device__ float4 g_v0[NPART];          // initial velocities
__device__ float4 g_F4[NPART][3];       // deformation gradient rows (w unused)
__device__ int4   g_baseh[2][NPART];    // base-cell history for re-zeroing

// ---------------- helpers ----------------
__device__ __forceinline__ float wsel(int o, float a, float b, float c) {
    return (o == 0) ? a : ((o == 1) ? b : c);
}

#define GRED8(v)                                              \
    do {                                                      \
        v += __shfl_xor_sync(0xffffffffu, v, 4);              \
        v += __shfl_xor_sync(0xffffffffu, v, 2);              \
        v += __shfl_xor_sync(0xffffffffu, v, 1);              \
    } while (0)

// ---------------- init kernels ----------------
__global__ void k_zero_grid() {
    int i = blockIdx.x * blockDim.x + threadIdx.x;
    if (i < 3 * G3) reinterpret_cast<float4*>(g_grid)[i] = make_float4(0.f, 0.f, 0.f, 0.f);
}

__global__ void k_init_part(const float* __restrict__ q, const float* __restrict__ qd) {
    int p = blockIdx.x * blockDim.x + threadIdx.x;
    if (p >= NPART) return;
    g_x4[p] = make_float4(q[p * 3 + 0], q[p * 3 + 1], q[p * 3 + 2], 0.f);
    g_v0[p] = make_float4(qd[p * 3 + 0], qd[p * 3 + 1], qd[p * 3 + 2], 0.f);
    g_F4[p][0] = make_float4(1.f, 0.f, 0.f, 0.f);
    g_F4[p][1] = make_float4(0.f, 1.f, 0.f, 0.f);
    g_F4[p][2] = make_float4(0.f, 0.f, 1.f, 0.f);
}

// ---------------- fused substep kernel: 8 lanes per particle ----------------
// lane layout: sub = lane>>3 selects particle (4 per warp), sl = lane&7;
// lane handles stencil cells sl, sl+8, sl+16, sl+24 (cells 27..31 inactive).
__global__ void __launch_bounds__(128) k_mpm_step(int t, const float* __restrict__ vptr) {
    unsigned gtid = blockIdx.x * blockDim.x + threadIdx.x;
    int wg = gtid >> 5;
    int lane = threadIdx.x & 31;
    int sub = lane >> 3;
    int sl = lane & 7;
    int p = wg * 4 + sub;
    if (p >= NPART) return;   // NPART % 4 == 0 -> whole-warp uniform exit

    const int bufG = (t + 2) % 3;   // gather buffer  (t-1 mod 3)
    const int bufS = t % 3;         // scatter buffer
    const int bufZ = (t + 1) % 3;   // buffer scattered at t-2 -> re-zero
    const float vscalar = __ldg(vptr);

    // --- zero the buffer used two substeps ago (touched cells only) ---
    if (t >= 3) {
        int4 ob = g_baseh[t & 1][p];
#pragma unroll
        for (int k = 0; k < 4; k++) {
            int c = sl + 8 * k;
            if (c < 27) {
                int oi = c / 9, r = c - 9 * oi, oj = r / 3, ok = r - 3 * oj;
                int nx = min(max(ob.x + oi, 0), G - 1);
                int ny = min(max(ob.y + oj, 0), G - 1);
                int nz = min(max(ob.z + ok, 0), G - 1);
                g_grid[bufZ][(nx * G + ny) * G + nz] = make_float4(0.f, 0.f, 0.f, 0.f);
            }
        }
    }

    float4 xr = g_x4[p];
    float px = xr.x, py = xr.y, pz = xr.z;

    float vx, vy, vz;
    float c00, c01, c02, c10, c11, c12, c20, c21, c22;

    if (t >= 2) {
        // --- G2P for substep t-1 (recompute weights from stored x) ---
        float gx = px * INVDX_, gy = py * INVDX_, gz = pz * INVDX_;
        float bxf = floorf(gx - 0.5f), byf = floorf(gy - 0.5f), bzf = floorf(gz - 0.5f);
        int bx = (int)bxf, by = (int)byf, bz = (int)bzf;
        float fx = gx - bxf, fy = gy - byf, fz = gz - bzf;

        float wx0 = 0.5f * (1.5f - fx) * (1.5f - fx);
        float wx1 = 0.75f - (fx - 1.0f) * (fx - 1.0f);
        float wx2 = 0.5f * (fx - 0.5f) * (fx - 0.5f);
        float wy0 = 0.5f * (1.5f - fy) * (1.5f - fy);
        float wy1 = 0.75f - (fy - 1.0f) * (fy - 1.0f);
        float wy2 = 0.5f * (fy - 0.5f) * (fy - 0.5f);
        float wz0 = 0.5f * (1.5f - fz) * (1.5f - fz);
        float wz1 = 0.75f - (fz - 1.0f) * (fz - 1.0f);
        float wz2 = 0.5f * (fz - 0.5f) * (fz - 0.5f);

        vx = vy = vz = 0.f;
        c00 = c01 = c02 = c10 = c11 = c12 = c20 = c21 = c22 = 0.f;

#pragma unroll
        for (int k = 0; k < 4; k++) {
            int c = sl + 8 * k;
            if (c < 27) {
                int oi = c / 9, r = c - 9 * oi, oj = r / 3, ok = r - 3 * oj;
                float w = wsel(oi, wx0, wx1, wx2) * wsel(oj, wy0, wy1, wy2) * wsel(ok, wz0, wz1, wz2);
                int nx = min(max(bx + oi, 0), G - 1);
                int ny = min(max(by + oj, 0), G - 1);
                int nz = min(max(bz + ok, 0), G - 1);
                float4 cell = g_grid[bufG][(nx * G + ny) * G + nz];

                float inv = __fdividef(1.0f, cell.w + vscalar);
                float gvx = cell.x * inv, gvy = cell.y * inv, gvz = cell.z * inv;
                if ((nx < BOUNDC && gvx < 0.f) || (nx >= G - BOUNDC && gvx > 0.f)) gvx = 0.f;
                if ((ny < BOUNDC && gvy < 0.f) || (ny >= G - BOUNDC && gvy > 0.f)) gvy = 0.f;
                if ((nz < BOUNDC && gvz < 0.f) || (nz >= G - BOUNDC && gvz > 0.f)) gvz = 0.f;

                float dpx = ((float)oi - fx) * DX_;
                float dpy = ((float)oj - fy) * DX_;
                float dpz = ((float)ok - fz) * DX_;

                float wgx = w * gvx, wgy = w * gvy, wgz = w * gvz;
                vx += wgx; vy += wgy; vz += wgz;
                c00 += wgx * dpx; c01 += wgx * dpy; c02 += wgx * dpz;
                c10 += wgy * dpx; c11 += wgy * dpy; c12 += wgy * dpz;
                c20 += wgz * dpx; c21 += wgz * dpy; c22 += wgz * dpz;
            }
        }

        GRED8(vx);  GRED8(vy);  GRED8(vz);
        GRED8(c00); GRED8(c01); GRED8(c02);
        GRED8(c10); GRED8(c11); GRED8(c12);
        GRED8(c20); GRED8(c21); GRED8(c22);

        c00 *= DINV_; c01 *= DINV_; c02 *= DINV_;
        c10 *= DINV_; c11 *= DINV_; c12 *= DINV_;
        c20 *= DINV_; c21 *= DINV_; c22 *= DINV_;

        px += DT_ * vx; py += DT_ * vy; pz += DT_ * vz;
    } else {
        float4 v0 = g_v0[p];
        vx = v0.x; vy = v0.y; vz = v0.z;
        c00 = c01 = c02 = c10 = c11 = c12 = c20 = c21 = c22 = 0.f;
    }

    // --- F update: F = (I + DT*C) * F ---
    float4 Fr0 = g_F4[p][0], Fr1 = g_F4[p][1], Fr2 = g_F4[p][2];
    float f00 = Fr0.x, f01 = Fr0.y, f02 = Fr0.z;
    float f10 = Fr1.x, f11 = Fr1.y, f12 = Fr1.z;
    float f20 = Fr2.x, f21 = Fr2.y, f22 = Fr2.z;

    float a00 = 1.0f + DT_ * c00, a01 = DT_ * c01, a02 = DT_ * c02;
    float a10 = DT_ * c10, a11 = 1.0f + DT_ * c11, a12 = DT_ * c12;
    float a20 = DT_ * c20, a21 = DT_ * c21, a22 = 1.0f + DT_ * c22;

    float F00 = a00 * f00 + a01 * f10 + a02 * f20;
    float F01 = a00 * f01 + a01 * f11 + a02 * f21;
    float F02 = a00 * f02 + a01 * f12 + a02 * f22;
    float F10 = a10 * f00 + a11 * f10 + a12 * f20;
    float F11 = a10 * f01 + a11 * f11 + a12 * f21;
    float F12 = a10 * f02 + a11 * f12 + a12 * f22;
    float F20 = a20 * f00 + a21 * f10 + a22 * f20;
    float F21 = a20 * f01 + a21 * f11 + a22 * f21;
    float F22 = a20 * f02 + a21 * f12 + a22 * f22;

    // --- neo-Hookean PK1 via cofactors ---
    float co00 = F11 * F22 - F12 * F21;
    float co01 = F12 * F20 - F10 * F22;
    float co02 = F10 * F21 - F11 * F20;
    float co10 = F02 * F21 - F01 * F22;
    float co11 = F00 * F22 - F02 * F20;
    float co12 = F01 * F20 - F00 * F21;
    float co20 = F01 * F12 - F02 * F11;
    float co21 = F02 * F10 - F00 * F12;
    float co22 = F00 * F11 - F01 * F10;
    float J = F00 * co00 + F01 * co01 + F02 * co02;

    float logJ = __logf(fmaxf(J, 1e-6f));
    float coef = __fdividef(LAM_ * logJ - MU_, J);   // P = MU*F + coef*cof(F)

    float P00 = MU_ * F00 + coef * co00;
    float P01 = MU_ * F01 + coef * co01;
    float P02 = MU_ * F02 + coef * co02;
    float P10 = MU_ * F10 + coef * co10;
    float P11 = MU_ * F11 + coef * co11;
    float P12 = MU_ * F12 + coef * co12;
    float P20 = MU_ * F20 + coef * co20;
    float P21 = MU_ * F21 + coef * co21;
    float P22 = MU_ * F22 + coef * co22;

    // affine = SPRE * P * F^T + PMASS * C
    float A00 = SPRE_ * (P00 * F00 + P01 * F01 + P02 * F02) + PMASS_ * c00;
    float A01 = SPRE_ * (P00 * F10 + P01 * F11 + P02 * F12) + PMASS_ * c01;
    float A02 = SPRE_ * (P00 * F20 + P01 * F21 + P02 * F22) + PMASS_ * c02;
    float A10 = SPRE_ * (P10 * F00 + P11 * F01 + P12 * F02) + PMASS_ * c10;
    float A11 = SPRE_ * (P10 * F10 + P11 * F11 + P12 * F12) + PMASS_ * c11;
    float A12 = SPRE_ * (P10 * F20 + P11 * F21 + P12 * F22) + PMASS_ * c12;
    float A20 = SPRE_ * (P20 * F00 + P21 * F01 + P22 * F02) + PMASS_ * c20;
    float A21 = SPRE_ * (P20 * F10 + P21 * F11 + P22 * F12) + PMASS_ * c21;
    float A22 = SPRE_ * (P20 * F20 + P21 * F21 + P22 * F22) + PMASS_ * c22;

    // --- P2G for substep t ---
    float gx2 = px * INVDX_, gy2 = py * INVDX_, gz2 = pz * INVDX_;
    float bxf2 = floorf(gx2 - 0.5f), byf2 = floorf(gy2 - 0.5f), bzf2 = floorf(gz2 - 0.5f);
    int bx2 = (int)bxf2, by2 = (int)byf2, bz2 = (int)bzf2;
    float fx2 = gx2 - bxf2, fy2 = gy2 - byf2, fz2 = gz2 - bzf2;

    float sx0 = 0.5f * (1.5f - fx2) * (1.5f - fx2);
    float sx1 = 0.75f - (fx2 - 1.0f) * (fx2 - 1.0f);
    float sx2 = 0.5f * (fx2 - 0.5f) * (fx2 - 0.5f);
    float sy0 = 0.5f * (1.5f - fy2) * (1.5f - fy2);
    float sy1 = 0.75f - (fy2 - 1.0f) * (fy2 - 1.0f);
    float sy2 = 0.5f * (fy2 - 0.5f) * (fy2 - 0.5f);
    float sz0 = 0.5f * (1.5f - fz2) * (1.5f - fz2);
    float sz1 = 0.75f - (fz2 - 1.0f) * (fz2 - 1.0f);
    float sz2 = 0.5f * (fz2 - 0.5f) * (fz2 - 0.5f);

    float mvx = PMASS_ * vx;
    float mvy = PMASS_ * (vy + DT_ * GRAVY_);
    float mvz = PMASS_ * vz;

    __syncwarp();  // all reads of g_baseh / g_F4 done before the overwrite below

    if (sl == 0) {
        g_x4[p] = make_float4(px, py, pz, 0.f);
        g_F4[p][0] = make_float4(F00, F01, F02, 0.f);
        g_F4[p][1] = make_float4(F10, F11, F12, 0.f);
        g_F4[p][2] = make_float4(F20, F21, F22, 0.f);
        g_baseh[t & 1][p] = make_int4(bx2, by2, bz2, 0);
    }

#pragma unroll
    for (int k = 0; k < 4; k++) {
        int c = sl + 8 * k;
        if (c < 27) {
            int oi = c / 9, r = c - 9 * oi, oj = r / 3, ok = r - 3 * oj;
            float w2 = wsel(oi, sx0, sx1, sx2) * wsel(oj, sy0, sy1, sy2) * wsel(ok, sz0, sz1, sz2);
            float dpx = ((float)oi - fx2) * DX_;
            float dpy = ((float)oj - fy2) * DX_;
            float dpz = ((float)ok - fz2) * DX_;

            float mx = w2 * (mvx + A00 * dpx + A01 * dpy + A02 * dpz);
            float my = w2 * (mvy + A10 * dpx + A11 * dpy + A12 * dpz);
            float mz = w2 * (mvz + A20 * dpx + A21 * dpy + A22 * dpz);
            float mw = w2 * PMASS_;

            int nx = min(max(bx2 + oi, 0), G - 1);
            int ny = min(max(by2 + oj, 0), G - 1);
            int nz = min(max(bz2 + ok, 0), G - 1);
            float4* cell = &g_grid[bufS][(nx * G + ny) * G + nz];
            asm volatile("red.global.add.v4.f32 [%0], {%1, %2, %3, %4};"
                         :: "l"(cell), "f"(mx), "f"(my), "f"(mz), "f"(mw)
                         : "memory");
        }
    }
}

// ---------------- frame output ----------------
__global__ void k_out_frame(float* __restrict__ out, const float* __restrict__ vptr, int buf) {
    int i = blockIdx.x * blockDim.x + threadIdx.x;
    if (i < G3) out[i] = g_grid[buf][i].w + vptr[0];
}

// ---------------- launcher ----------------
extern "C" void kernel_launch(void* const* d_in, const int* in_sizes, int n_in,
                              void* d_out, int out_size) {
    const float* v  = (const float*)d_in[0];
    const float* q  = (const float*)d_in[1];
    const float* qd = (const float*)d_in[2];
    float* out = (float*)d_out;
    (void)in_sizes; (void)n_in; (void)out_size;

    k_zero_grid<<<(3 * G3 + 255) / 256, 256>>>();
    k_init_part<<<(NPART + 127) / 128, 128>>>(q, qd);

    const int blocks = (NPART * 8 + 127) / 128;  // 8 lanes per particle
    for (int t = 1; t <= NSUB; t++) {
        k_mpm_step<<<blocks, 128>>>(t, v);
        if (t % SPF == 0) {
            int f = t / SPF - 1;
            k_out_frame<<<(G3 + 255) / 256, 256>>>(out + (size_t)f * G3, v, t % 3);
        }
    }
}

// round 4
// speedup vs baseline: 3.2658x; 1.0823x over previous
#include <cuda_runtime.h>

// ---------------- constants ----------------
#define G       100
#define G3      (G * G * G)
#define NPART   13500
#define NSUB    600
#define SPF     30
#define BOUNDC  3
#define NTHR    128
#define NBLK    ((NPART * 8 + NTHR - 1) / NTHR)   // 844

#define DT_     5e-4f
#define INVDX_  100.0f
#define DX_     0.01f
#define MU_     (1.0e5f / 2.6f)
#define LAM_    (0.3e5f / 0.52f)
#define PVOL_   (0.005f * 0.005f * 0.005f)
#define PMASS_  (PVOL_ * 3000.0f)
#define SPRE_   (-DT_ * PVOL_ * 4.0f * INVDX_ * INVDX_)
#define DINV_   (4.0f * INVDX_ * INVDX_)
#define GRAVY_  (-9.8f)

// ---------------- persistent device state ----------------
__device__ float4 g_grid[3][G3];          // (vx,vy,vz,m) x 3 rotating buffers
__device__ unsigned g_bar_count;          // grid barrier arrive counter
__device__ volatile unsigned g_bar_gen;   // grid barrier generation

// ---------------- helpers ----------------
__device__ __forceinline__ float wsel(int o, float a, float b, float c) {
    return (o == 0) ? a : ((o == 1) ? b : c);
}

#define GRED8(v)                                              \
    do {                                                      \
        v += __shfl_xor_sync(0xffffffffu, v, 4);              \
        v += __shfl_xor_sync(0xffffffffu, v, 2);              \
        v += __shfl_xor_sync(0xffffffffu, v, 1);              \
    } while (0)

// release/acquire grid-wide barrier (all NBLK blocks co-resident by launch_bounds)
__device__ __forceinline__ void grid_barrier() {
    __syncthreads();
    if (threadIdx.x == 0) {
        __threadfence();                                   // release prior writes
        unsigned gen = g_bar_gen;                          // read before arrive (safe: release needs our add)
        if (atomicAdd(&g_bar_count, 1u) == NBLK - 1) {
            g_bar_count = 0;
            __threadfence();
            g_bar_gen = gen + 1;
        } else {
            while (g_bar_gen == gen) __nanosleep(32);
        }
        __threadfence();                                   // acquire
    }
    __syncthreads();
}

// ---------------- the megakernel ----------------
__global__ void __launch_bounds__(NTHR, 7) k_mpm_mega(
    const float* __restrict__ vptr, const float* __restrict__ q,
    const float* __restrict__ qd, float* __restrict__ out)
{
    const int tid = blockIdx.x * NTHR + threadIdx.x;
    const int lane = threadIdx.x & 31;
    const int sl = lane & 7;
    const int p = (tid >> 5) * 4 + (lane >> 3);
    const bool active = (p < NPART);
    const float vscalar = __ldg(vptr);
    const float4 zero4 = make_float4(0.f, 0.f, 0.f, 0.f);

    // stencil-cell decode for this lane's 4 cells (hoisted, constant all run)
    int OI[4], OJ[4], OK[4];
    bool CA[4];
#pragma unroll
    for (int k = 0; k < 4; k++) {
        int c = sl + 8 * k;
        CA[k] = (c < 27);
        int ci = c < 27 ? c : 0;
        OI[k] = ci / 9;
        OJ[k] = (ci / 3) % 3;
        OK[k] = ci % 3;
    }

    // ---- init: zero all 3 grid buffers ----
    for (int i = tid; i < 3 * G3; i += NBLK * NTHR)
        __stcg(&reinterpret_cast<float4*>(g_grid)[i], zero4);

    // ---- init particle state (registers, persistent for the whole run) ----
    float px = 0.f, py = 0.f, pz = 0.f, v0x = 0.f, v0y = 0.f, v0z = 0.f;
    if (active) {
        px = __ldg(&q[p * 3 + 0]);  py = __ldg(&q[p * 3 + 1]);  pz = __ldg(&q[p * 3 + 2]);
        v0x = __ldg(&qd[p * 3 + 0]); v0y = __ldg(&qd[p * 3 + 1]); v0z = __ldg(&qd[p * 3 + 2]);
    }
    float F00 = 1.f, F01 = 0.f, F02 = 0.f;
    float F10 = 0.f, F11 = 1.f, F12 = 0.f;
    float F20 = 0.f, F21 = 0.f, F22 = 1.f;
    int bh_old = 0, bh_new = 0;   // packed base-cell history (7 bits/axis)

    grid_barrier();   // grids zeroed everywhere

#pragma unroll 1
    for (int t = 1; t <= NSUB; t++) {
        const int bufG = (t + 2) % 3;   // gather  (t-1 mod 3)
        const int bufS = t % 3;         // scatter
        const int bufZ = (t + 1) % 3;   // zero    (scattered at t-2)

        if (active) {
            // --- zero touched cells of the t-2 buffer ---
            if (t >= 3) {
                int obz = bh_old & 127, oby = (bh_old >> 7) & 127, obx = (bh_old >> 14) & 127;
#pragma unroll
                for (int k = 0; k < 4; k++) if (CA[k]) {
                    int nx = min(max(obx - 1 + OI[k], 0), G - 1);
                    int ny = min(max(oby - 1 + OJ[k], 0), G - 1);
                    int nz = min(max(obz - 1 + OK[k], 0), G - 1);
                    __stcg(&g_grid[bufZ][(nx * G + ny) * G + nz], zero4);
                }
            }

            float vx, vy, vz;
            float c00, c01, c02, c10, c11, c12, c20, c21, c22;

            if (t >= 2) {
                // --- G2P for substep t-1 ---
                float gx = px * INVDX_, gy = py * INVDX_, gz = pz * INVDX_;
                float bxf = floorf(gx - 0.5f), byf = floorf(gy - 0.5f), bzf = floorf(gz - 0.5f);
                int bx = (int)bxf, by = (int)byf, bz = (int)bzf;
                float fx = gx - bxf, fy = gy - byf, fz = gz - bzf;

                float wx0 = 0.5f * (1.5f - fx) * (1.5f - fx);
                float wx1 = 0.75f - (fx - 1.0f) * (fx - 1.0f);
                float wx2 = 0.5f * (fx - 0.5f) * (fx - 0.5f);
                float wy0 = 0.5f * (1.5f - fy) * (1.5f - fy);
                float wy1 = 0.75f - (fy - 1.0f) * (fy - 1.0f);
                float wy2 = 0.5f * (fy - 0.5f) * (fy - 0.5f);
                float wz0 = 0.5f * (1.5f - fz) * (1.5f - fz);
                float wz1 = 0.75f - (fz - 1.0f) * (fz - 1.0f);
                float wz2 = 0.5f * (fz - 0.5f) * (fz - 0.5f);

                vx = vy = vz = 0.f;
                c00 = c01 = c02 = c10 = c11 = c12 = c20 = c21 = c22 = 0.f;

#pragma unroll
                for (int k = 0; k < 4; k++) if (CA[k]) {
                    int oi = OI[k], oj = OJ[k], ok = OK[k];
                    float w = wsel(oi, wx0, wx1, wx2) * wsel(oj, wy0, wy1, wy2) * wsel(ok, wz0, wz1, wz2);
                    int nx = min(max(bx + oi, 0), G - 1);
                    int ny = min(max(by + oj, 0), G - 1);
                    int nz = min(max(bz + ok, 0), G - 1);
                    float4 cell = __ldcg(&g_grid[bufG][(nx * G + ny) * G + nz]);

                    float inv = __fdividef(1.0f, cell.w + vscalar);
                    float gvx = cell.x * inv, gvy = cell.y * inv, gvz = cell.z * inv;
                    if ((nx < BOUNDC && gvx < 0.f) || (nx >= G - BOUNDC && gvx > 0.f)) gvx = 0.f;
                    if ((ny < BOUNDC && gvy < 0.f) || (ny >= G - BOUNDC && gvy > 0.f)) gvy = 0.f;
                    if ((nz < BOUNDC && gvz < 0.f) || (nz >= G - BOUNDC && gvz > 0.f)) gvz = 0.f;

                    float dpx = ((float)oi - fx) * DX_;
                    float dpy = ((float)oj - fy) * DX_;
                    float dpz = ((float)ok - fz) * DX_;

                    float wgx = w * gvx, wgy = w * gvy, wgz = w * gvz;
                    vx += wgx; vy += wgy; vz += wgz;
                    c00 += wgx * dpx; c01 += wgx * dpy; c02 += wgx * dpz;
                    c10 += wgy * dpx; c11 += wgy * dpy; c12 += wgy * dpz;
                    c20 += wgz * dpx; c21 += wgz * dpy; c22 += wgz * dpz;
                }

                GRED8(vx);  GRED8(vy);  GRED8(vz);
                GRED8(c00); GRED8(c01); GRED8(c02);
                GRED8(c10); GRED8(c11); GRED8(c12);
                GRED8(c20); GRED8(c21); GRED8(c22);

                c00 *= DINV_; c01 *= DINV_; c02 *= DINV_;
                c10 *= DINV_; c11 *= DINV_; c12 *= DINV_;
                c20 *= DINV_; c21 *= DINV_; c22 *= DINV_;

                px += DT_ * vx; py += DT_ * vy; pz += DT_ * vz;
            } else {
                vx = v0x; vy = v0y; vz = v0z;
                c00 = c01 = c02 = c10 = c11 = c12 = c20 = c21 = c22 = 0.f;
            }

            // --- F = (I + DT*C) * F ---
            float a00 = 1.0f + DT_ * c00, a01 = DT_ * c01, a02 = DT_ * c02;
            float a10 = DT_ * c10, a11 = 1.0f + DT_ * c11, a12 = DT_ * c12;
            float a20 = DT_ * c20, a21 = DT_ * c21, a22 = 1.0f + DT_ * c22;

            float N00 = a00 * F00 + a01 * F10 + a02 * F20;
            float N01 = a00 * F01 + a01 * F11 + a02 * F21;
            float N02 = a00 * F02 + a01 * F12 + a02 * F22;
            float N10 = a10 * F00 + a11 * F10 + a12 * F20;
            float N11 = a10 * F01 + a11 * F11 + a12 * F21;
            float N12 = a10 * F02 + a11 * F12 + a12 * F22;
            float N20 = a20 * F00 + a21 * F10 + a22 * F20;
            float N21 = a20 * F01 + a21 * F11 + a22 * F21;
            float N22 = a20 * F02 + a21 * F12 + a22 * F22;
            F00 = N00; F01 = N01; F02 = N02;
            F10 = N10; F11 = N11; F12 = N12;
            F20 = N20; F21 = N21; F22 = N22;

            // --- neo-Hookean PK1 via cofactors ---
            float co00 = F11 * F22 - F12 * F21;
            float co01 = F12 * F20 - F10 * F22;
            float co02 = F10 * F21 - F11 * F20;
            float co10 = F02 * F21 - F01 * F22;
            float co11 = F00 * F22 - F02 * F20;
            float co12 = F01 * F20 - F00 * F21;
            float co20 = F01 * F12 - F02 * F11;
            float co21 = F02 * F10 - F00 * F12;
            float co22 = F00 * F11 - F01 * F10;
            float J = F00 * co00 + F01 * co01 + F02 * co02;

            float logJ = __logf(fmaxf(J, 1e-6f));
            float coef = __fdividef(LAM_ * logJ - MU_, J);

            float P00 = MU_ * F00 + coef * co00;
            float P01 = MU_ * F01 + coef * co01;
            float P02 = MU_ * F02 + coef * co02;
            float P10 = MU_ * F10 + coef * co10;
            float P11 = MU_ * F11 + coef * co11;
            float P12 = MU_ * F12 + coef * co12;
            float P20 = MU_ * F20 + coef * co20;
            float P21 = MU_ * F21 + coef * co21;
            float P22 = MU_ * F22 + coef * co22;

            float A00 = SPRE_ * (P00 * F00 + P01 * F01 + P02 * F02) + PMASS_ * c00;
            float A01 = SPRE_ * (P00 * F10 + P01 * F11 + P02 * F12) + PMASS_ * c01;
            float A02 = SPRE_ * (P00 * F20 + P01 * F21 + P02 * F22) + PMASS_ * c02;
            float A10 = SPRE_ * (P10 * F00 + P11 * F01 + P12 * F02) + PMASS_ * c10;
            float A11 = SPRE_ * (P10 * F10 + P11 * F11 + P12 * F12) + PMASS_ * c11;
            float A12 = SPRE_ * (P10 * F20 + P11 * F21 + P12 * F22) + PMASS_ * c12;
            float A20 = SPRE_ * (P20 * F00 + P21 * F01 + P22 * F02) + PMASS_ * c20;
            float A21 = SPRE_ * (P20 * F10 + P21 * F11 + P22 * F12) + PMASS_ * c21;
            float A22 = SPRE_ * (P20 * F20 + P21 * F21 + P22 * F22) + PMASS_ * c22;

            // --- P2G for substep t ---
            float gx2 = px * INVDX_, gy2 = py * INVDX_, gz2 = pz * INVDX_;
            float bxf2 = floorf(gx2 - 0.5f), byf2 = floorf(gy2 - 0.5f), bzf2 = floorf(gz2 - 0.5f);
            int bx2 = (int)bxf2, by2 = (int)byf2, bz2 = (int)bzf2;
            float fx2 = gx2 - bxf2, fy2 = gy2 - byf2, fz2 = gz2 - bzf2;

            float sx0 = 0.5f * (1.5f - fx2) * (1.5f - fx2);
            float sx1 = 0.75f - (fx2 - 1.0f) * (fx2 - 1.0f);
            float sx2 = 0.5f * (fx2 - 0.5f) * (fx2 - 0.5f);
            float sy0 = 0.5f * (1.5f - fy2) * (1.5f - fy2);
            float sy1 = 0.75f - (fy2 - 1.0f) * (fy2 - 1.0f);
            float sy2 = 0.5f * (fy2 - 0.5f) * (fy2 - 0.5f);
            float sz0 = 0.5f * (1.5f - fz2) * (1.5f - fz2);
            float sz1 = 0.75f - (fz2 - 1.0f) * (fz2 - 1.0f);
            float sz2 = 0.5f * (fz2 - 0.5f) * (fz2 - 0.5f);

            float mvx = PMASS_ * vx;
            float mvy = PMASS_ * (vy + DT_ * GRAVY_);
            float mvz = PMASS_ * vz;

            bh_old = bh_new;
            bh_new = ((bx2 + 1) << 14) | ((by2 + 1) << 7) | (bz2 + 1);  // +1 bias keeps fields >= 0

#pragma unroll
            for (int k = 0; k < 4; k++) if (CA[k]) {
                int oi = OI[k], oj = OJ[k], ok = OK[k];
                float w2 = wsel(oi, sx0, sx1, sx2) * wsel(oj, sy0, sy1, sy2) * wsel(ok, sz0, sz1, sz2);
                float dpx = ((float)oi - fx2) * DX_;
                float dpy = ((float)oj - fy2) * DX_;
                float dpz = ((float)ok - fz2) * DX_;

                float mx = w2 * (mvx + A00 * dpx + A01 * dpy + A02 * dpz);
                float my = w2 * (mvy + A10 * dpx + A11 * dpy + A12 * dpz);
                float mz = w2 * (mvz + A20 * dpx + A21 * dpy + A22 * dpz);
                float mw = w2 * PMASS_;

                int nx = min(max(bx2 + oi, 0), G - 1);
                int ny = min(max(by2 + oj, 0), G - 1);
                int nz = min(max(bz2 + ok, 0), G - 1);
                float4* cell = &g_grid[bufS][(nx * G + ny) * G + nz];
                asm volatile("red.global.add.v4.f32 [%0], {%1, %2, %3, %4};"
                             :: "l"(cell), "f"(mx), "f"(my), "f"(mz), "f"(mw)
                             : "memory");
            }
        }

        grid_barrier();   // scatters of substep t complete

        // --- frame output (after barrier; safe vs zeroing which happens at t+2) ---
        if (t % SPF == 0) {
            const int f = t / SPF - 1;
            float* dst = out + (size_t)f * G3;
            const float4* src = g_grid[bufS];
            for (int i = tid; i < G3; i += NBLK * NTHR)
                dst[i] = __ldcg(&src[i].w) + vscalar;
        }
    }
}

// ---------------- launcher ----------------
extern "C" void kernel_launch(void* const* d_in, const int* in_sizes, int n_in,
                              void* d_out, int out_size) {
    const float* v  = (const float*)d_in[0];
    const float* q  = (const float*)d_in[1];
    const float* qd = (const float*)d_in[2];
    float* out = (float*)d_out;
    (void)in_sizes; (void)n_in; (void)out_size;

    k_mpm_mega<<<NBLK, NTHR>>>(v, q, qd, out);
}